// round 16
// baseline (speedup 1.0000x reference)
#include <cuda_runtime.h>
#include <cuda_bf16.h>
#include <cuda_fp16.h>

#define BATCH   2048
#define NTOK    49
#define CH      512
#define NHEADS  4
#define KDIM    32
#define DV      128
#define QO      192
#define EPS     1e-5f
#define FST     136
#define KQS     40
#define ATS     72
#define YQS     36
#define NROWS   ((size_t)BATCH * NTOK)

// -------- global scratch --------
// h fp16, A-fragment-paired: [m16tile][ks(32)][lane(32)] uint4
//   uint4 = {kpair@er, kpair@er+8, k8pair@er, k8pair@er+8}, lane = er*4 + quad
__device__ __align__(16) uint4 g_hA[(NROWS / 16) * 32 * 32];
// proj weights fp16, n32-grouped: [n32(16)][ks(32)][lane(32)][sub(4)] uint2
__device__ __align__(16) uint2 g_wBh[16 * 32 * 32 * 4];
// qkv weights fp16, B-fragment permuted
__device__ __align__(16) uint2 g_qwBh[NHEADS * 24 * 8 * 32];

// ==================== helpers ====================
__device__ __forceinline__ unsigned s2u(const void* p) {
    return (unsigned)__cvta_generic_to_shared(p);
}
__device__ __forceinline__ void ldsm_x4(unsigned* r, unsigned addr) {
    asm volatile("ldmatrix.sync.aligned.m8n8.x4.shared.b16 {%0,%1,%2,%3}, [%4];"
        : "=r"(r[0]), "=r"(r[1]), "=r"(r[2]), "=r"(r[3]) : "r"(addr));
}
__device__ __forceinline__ void ldsm_x4_t(unsigned* r, unsigned addr) {
    asm volatile("ldmatrix.sync.aligned.m8n8.x4.trans.shared.b16 {%0,%1,%2,%3}, [%4];"
        : "=r"(r[0]), "=r"(r[1]), "=r"(r[2]), "=r"(r[3]) : "r"(addr));
}
__device__ __forceinline__ void mma16816h(float* c, const unsigned* a, const unsigned* b) {
    asm volatile("mma.sync.aligned.m16n8k16.row.col.f32.f16.f16.f32 "
        "{%0,%1,%2,%3}, {%4,%5,%6,%7}, {%8,%9}, {%0,%1,%2,%3};"
        : "+f"(c[0]), "+f"(c[1]), "+f"(c[2]), "+f"(c[3])
        : "r"(a[0]), "r"(a[1]), "r"(a[2]), "r"(a[3]), "r"(b[0]), "r"(b[1]));
}
__device__ __forceinline__ unsigned packh2(__half a, __half b) {
    __half2 p = __halves2half2(a, b);
    return *reinterpret_cast<unsigned*>(&p);
}
__device__ __forceinline__ void split2h(float v0, float v1, unsigned& hp, unsigned& lp) {
    __half h0 = __float2half_rn(v0), h1 = __float2half_rn(v1);
    __half l0 = __float2half_rn(v0 - __half2float(h0));
    __half l1 = __float2half_rn(v1 - __half2float(h1));
    hp = packh2(h0, h1);
    lp = packh2(l0, l1);
}
__device__ __forceinline__ void recon2h(unsigned hp, unsigned lp, float& v0, float& v1) {
    __half2 h = *reinterpret_cast<__half2*>(&hp);
    __half2 l = *reinterpret_cast<__half2*>(&lp);
    v0 = __low2float(h) + __low2float(l);
    v1 = __high2float(h) + __high2float(l);
}

// ==================== prep kernels ====================
__global__ void wsplit_kernel(const float* __restrict__ w) {
    int i = blockIdx.x * 256 + threadIdx.x;        // 65536 uint2 entries
    int j0 = i >> 10;          // n8 tile 0..63
    int s_ = (i >> 5) & 31;    // ks
    int l  = i & 31;
    int n  = j0 * 8 + (l >> 2);
    int k0 = s_ * 16 + (l & 3) * 2;
    float a0 = w[n * 512 + k0],     a1 = w[n * 512 + k0 + 1];
    float a2 = w[n * 512 + k0 + 8], a3 = w[n * 512 + k0 + 9];
    uint2 p;
    p.x = packh2(__float2half_rn(a0), __float2half_rn(a1));
    p.y = packh2(__float2half_rn(a2), __float2half_rn(a3));
    int n32 = j0 >> 2, sub = j0 & 3;
    g_wBh[((n32 * 32 + s_) * 32 + l) * 4 + sub] = p;
}

__global__ void qkvsplit_kernel(const float* __restrict__ w) {
    int i = blockIdx.x * 256 + threadIdx.x;
    int h = i / (192 * 64);
    int rem = i % (192 * 64);
    int n = rem / 64;
    int p = rem % 64;
    float v0 = w[((size_t)h * 192 + n) * 128 + p * 2];
    float v1 = w[((size_t)h * 192 + n) * 128 + p * 2 + 1];
    unsigned hi = packh2(__float2half_rn(v0), __float2half_rn(v1));
    int j = n >> 3, kstep = p >> 3, q = p & 7;
    int r = q >> 2, lm4 = q & 3;
    int lane = (n & 7) * 4 + lm4;
    int base = ((h * 24 + j) * 8 + kstep) * 32 + lane;
    reinterpret_cast<unsigned*>(g_qwBh)[base * 2 + r] = hi;
}

// ==================== Phase A: cascaded heads (fp16 pipeline) ====================

struct __align__(16) SmemA {
    __half ah[64 * FST], al[64 * FST];
    __half vh[64 * FST];
    union U1 {
        struct { __half kh[64 * KQS],
                        qh[64 * KQS], ql[64 * KQS]; } s1;
        struct { __half ath[64 * ATS]; } s2;
    } u1;
    float yq[49 * YQS];
    float dww[25 * 32];
    float qscale[NHEADS * QO], qbias[NHEADS * QO];
    float dws[NHEADS * KDIM], dwb[NHEADS * KDIM];
    float ab[NHEADS * NTOK];
    unsigned char bidx[3200];
};

__global__ void __launch_bounds__(256, 2) cascade_kernel(
    const float* __restrict__ x,
    const float* __restrict__ qkv_g,  const float* __restrict__ qkv_b,
    const float* __restrict__ qkv_m,  const float* __restrict__ qkv_v,
    const float* __restrict__ dw_w,   const float* __restrict__ dw_g,
    const float* __restrict__ dw_b,   const float* __restrict__ dw_m,
    const float* __restrict__ dw_v,   const float* __restrict__ attn_bias,
    const int* __restrict__ bias_idxs)
{
    extern __shared__ unsigned char smem_raw[];
    SmemA& s = *reinterpret_cast<SmemA*>(smem_raw);
    const int t    = threadIdx.x;
    const int b    = blockIdx.x;
    const int lane = t & 31;
    const int warp = t >> 5;
    const float scale = rsqrtf((float)KDIM);
    const size_t xoff = (size_t)b * NTOK * CH;

    for (int j = t; j < NHEADS * NTOK; j += 256) s.ab[j] = attn_bias[j];
    for (int j = t; j < NTOK * NTOK; j += 256) s.bidx[j] = (unsigned char)bias_idxs[j];
    for (int j = t; j < NHEADS * QO; j += 256) {
        float sc = qkv_g[j] * rsqrtf(qkv_v[j] + EPS);
        s.qscale[j] = sc;
        s.qbias[j]  = qkv_b[j] - qkv_m[j] * sc;
    }
    if (t < NHEADS * KDIM) {
        float sc = dw_g[t] * rsqrtf(dw_v[t] + EPS);
        s.dws[t] = sc;
        s.dwb[t] = dw_b[t] - dw_m[t] * sc;
    }
    for (int j = t; j < 15 * FST; j += 256) {
        __half z = __float2half_rn(0.f);
        s.ah[49 * FST + j] = z; s.al[49 * FST + j] = z;
        s.vh[49 * FST + j] = z;
    }
    for (int c = t; c < 1568; c += 256) {
        int n = c >> 5, d4 = (c & 31) * 4;
        float4 xv = *reinterpret_cast<const float4*>(&x[xoff + n * CH + d4]);
        unsigned hp0, lp0, hp1, lp1;
        split2h(xv.x, xv.y, hp0, lp0);
        split2h(xv.z, xv.w, hp1, lp1);
        *reinterpret_cast<uint2*>(&s.ah[n * FST + d4]) = make_uint2(hp0, hp1);
        *reinterpret_cast<uint2*>(&s.al[n * FST + d4]) = make_uint2(lp0, lp1);
    }

    const int a_r = lane & 15, a_c = (lane >> 4) * 8;
    const int b_r = (lane & 7) + ((lane & 16) ? 8 : 0);
    const int b_c = (lane & 8) ? 8 : 0;
    __syncthreads();

    for (int head = 0; head < NHEADS; ++head) {
        for (int j = t; j < KDIM * 25; j += 256) {
            int c = j / 25, tap = j % 25;
            s.dww[tap * 32 + c] = dw_w[(head * KDIM + c) * 25 + tap];
        }

        // ================= qkv GEMM (fp16 2-term) =================
        {
            float qacc[4][3][4];
            #pragma unroll
            for (int m = 0; m < 4; ++m)
                #pragma unroll
                for (int j = 0; j < 3; ++j)
                    #pragma unroll
                    for (int q = 0; q < 4; ++q) qacc[m][j][q] = 0.f;

            const int wbase = (head * 24 + warp * 3) * 8;
            uint2 b0[3], b1[3];
            #pragma unroll
            for (int j = 0; j < 3; ++j) {
                b0[j] = g_qwBh[(wbase + j * 8 + 0) * 32 + lane];
                b1[j] = g_qwBh[(wbase + j * 8 + 1) * 32 + lane];
            }
            #pragma unroll
            for (int k = 0; k < 8; ++k) {
                uint2 tb[3];
                if (k < 6) {
                    #pragma unroll
                    for (int j = 0; j < 3; ++j)
                        tb[j] = g_qwBh[(wbase + j * 8 + k + 2) * 32 + lane];
                }
                uint2* bc = (k & 1) ? b1 : b0;
                #pragma unroll
                for (int m = 0; m < 4; ++m) {
                    unsigned Ah[4], Al[4];
                    ldsm_x4(Ah, s2u(&s.ah[(m * 16 + a_r) * FST + k * 16 + a_c]));
                    ldsm_x4(Al, s2u(&s.al[(m * 16 + a_r) * FST + k * 16 + a_c]));
                    #pragma unroll
                    for (int j = 0; j < 3; ++j) {
                        mma16816h(qacc[m][j], Ah, reinterpret_cast<const unsigned*>(&bc[j]));
                        mma16816h(qacc[m][j], Al, reinterpret_cast<const unsigned*>(&bc[j]));
                    }
                }
                if (k < 6) {
                    #pragma unroll
                    for (int j = 0; j < 3; ++j) {
                        if (k & 1) b1[j] = tb[j]; else b0[j] = tb[j];
                    }
                }
            }
            const float* qsc = s.qscale + head * QO;
            const float* qbs = s.qbias  + head * QO;
            #pragma unroll
            for (int m = 0; m < 4; ++m) {
                int rb = m * 16 + (lane >> 2);
                #pragma unroll
                for (int j = 0; j < 3; ++j) {
                    int c0 = warp * 24 + j * 8 + (lane & 3) * 2;
                    float sc0 = qsc[c0], sc1 = qsc[c0 + 1];
                    float bb0 = qbs[c0], bb1 = qbs[c0 + 1];
                    #pragma unroll
                    for (int h2 = 0; h2 < 2; ++h2) {
                        int r = rb + h2 * 8;
                        if (r < NTOK) {
                            float y0 = qacc[m][j][h2 * 2 + 0] * sc0 + bb0;
                            float y1 = qacc[m][j][h2 * 2 + 1] * sc1 + bb1;
                            if (c0 < 32) {
                                s.yq[r * YQS + c0]     = y0;
                                s.yq[r * YQS + c0 + 1] = y1;
                            } else if (c0 < 64) {
                                *reinterpret_cast<unsigned*>(&s.u1.s1.kh[r * KQS + c0 - 32]) =
                                    packh2(__float2half_rn(y0), __float2half_rn(y1));
                            } else {
                                *reinterpret_cast<unsigned*>(&s.vh[r * FST + c0 - 64]) =
                                    packh2(__float2half_rn(y0), __float2half_rn(y1));
                            }
                        }
                    }
                }
            }
        }
        __syncthreads();

        // ================= conv (+BN) + coalesced x_next staging =================
        if (head < NHEADS - 1) {
            for (int c = t; c < 1568; c += 256) {
                int n = c >> 5, d4 = (c & 31) * 4;
                float4 xv = *reinterpret_cast<const float4*>(
                    &x[xoff + n * CH + (head + 1) * 128 + d4]);
                unsigned hp0, lp0, hp1, lp1;
                split2h(xv.x, xv.y, hp0, lp0);
                split2h(xv.z, xv.w, hp1, lp1);
                *reinterpret_cast<uint2*>(&s.ah[n * FST + d4]) = make_uint2(hp0, hp1);
                *reinterpret_cast<uint2*>(&s.al[n * FST + d4]) = make_uint2(lp0, lp1);
            }
        }
        for (int idx = t; idx < 392; idx += 256) {
            int n = idx >> 3, g = (idx & 7) * 4;
            int r = n / 7, sc_ = n % 7;
            float s0 = 0.f, s1 = 0.f, s2v = 0.f, s3 = 0.f;
            #pragma unroll
            for (int a = 0; a < 5; ++a) {
                int rr = r + a - 2;
                if ((unsigned)rr < 7u) {
                    #pragma unroll
                    for (int bb = 0; bb < 5; ++bb) {
                        int ss = sc_ + bb - 2;
                        if ((unsigned)ss < 7u) {
                            float4 yv = *reinterpret_cast<const float4*>(
                                &s.yq[(rr * 7 + ss) * YQS + g]);
                            float4 wv = *reinterpret_cast<const float4*>(
                                &s.dww[(a * 5 + bb) * 32 + g]);
                            s0 += yv.x * wv.x; s1 += yv.y * wv.y;
                            s2v += yv.z * wv.z; s3 += yv.w * wv.w;
                        }
                    }
                }
            }
            float4 dsv = *reinterpret_cast<const float4*>(&s.dws[head * KDIM + g]);
            float4 dbv = *reinterpret_cast<const float4*>(&s.dwb[head * KDIM + g]);
            float q0 = s0 * dsv.x + dbv.x, q1 = s1 * dsv.y + dbv.y;
            float q2 = s2v * dsv.z + dbv.z, q3 = s3 * dsv.w + dbv.w;
            unsigned hp0, lp0, hp1, lp1;
            split2h(q0, q1, hp0, lp0);
            split2h(q2, q3, hp1, lp1);
            *reinterpret_cast<uint2*>(&s.u1.s1.qh[n * KQS + g]) = make_uint2(hp0, hp1);
            *reinterpret_cast<uint2*>(&s.u1.s1.ql[n * KQS + g]) = make_uint2(lp0, lp1);
        }
        __syncthreads();

        // ================= qk scores (fp16 2-term) + in-register softmax =================
        if (warp < 4) {
            const int wm = warp * 16;
            float sacc[8][4];
            #pragma unroll
            for (int nt = 0; nt < 8; ++nt)
                #pragma unroll
                for (int q = 0; q < 4; ++q) sacc[nt][q] = 0.f;

            #pragma unroll
            for (int k16 = 0; k16 < 2; ++k16) {
                unsigned Ah[4], Al[4];
                ldsm_x4(Ah, s2u(&s.u1.s1.qh[(wm + a_r) * KQS + k16 * 16 + a_c]));
                ldsm_x4(Al, s2u(&s.u1.s1.ql[(wm + a_r) * KQS + k16 * 16 + a_c]));
                unsigned Bh[4][4];
                #pragma unroll
                for (int g = 0; g < 4; ++g)
                    ldsm_x4(Bh[g], s2u(&s.u1.s1.kh[(g * 16 + b_r) * KQS + k16 * 16 + b_c]));
                #pragma unroll
                for (int nt = 0; nt < 8; ++nt) {
                    const unsigned* bh = &Bh[nt >> 1][(nt & 1) * 2];
                    mma16816h(sacc[nt], Ah, bh);
                    mma16816h(sacc[nt], Al, bh);
                }
            }
            asm volatile("bar.sync 1, 128;" ::: "memory");

            const float* abr = s.ab + head * NTOK;
            const int r0 = wm + (lane >> 2);
            const int cq = (lane & 3) * 2;
            #pragma unroll
            for (int h2 = 0; h2 < 2; ++h2) {
                int r = r0 + h2 * 8;
                int rbase = r * 49;
                float v[16];
                #pragma unroll
                for (int nt = 0; nt < 8; ++nt) {
                    #pragma unroll
                    for (int q = 0; q < 2; ++q) {
                        int c = nt * 8 + cq + q;
                        v[nt * 2 + q] = (c < NTOK)
                            ? fmaf(sacc[nt][h2 * 2 + q], scale, abr[s.bidx[rbase + c]])
                            : -1e30f;
                    }
                }
                float mx = v[0];
                #pragma unroll
                for (int i = 1; i < 16; ++i) mx = fmaxf(mx, v[i]);
                mx = fmaxf(mx, __shfl_xor_sync(0xffffffffu, mx, 1));
                mx = fmaxf(mx, __shfl_xor_sync(0xffffffffu, mx, 2));
                float sm = 0.f;
                #pragma unroll
                for (int i = 0; i < 16; ++i) { v[i] = __expf(v[i] - mx); sm += v[i]; }
                sm += __shfl_xor_sync(0xffffffffu, sm, 1);
                sm += __shfl_xor_sync(0xffffffffu, sm, 2);
                float inv = __frcp_rn(sm);
                #pragma unroll
                for (int nt = 0; nt < 8; ++nt) {
                    *reinterpret_cast<unsigned*>(&s.u1.s2.ath[r * ATS + nt * 8 + cq]) =
                        packh2(__float2half_rn(v[nt * 2] * inv),
                               __float2half_rn(v[nt * 2 + 1] * inv));
                }
            }
        }
        __syncthreads();

        // ================= attn @ v (fp16 1-term probs) + staged-x add =================
        {
            const int wm2 = (warp & 1) * 32, wn2 = (warp >> 1) * 32;
            float facc[2][4][4];
            #pragma unroll
            for (int mt = 0; mt < 2; ++mt)
                #pragma unroll
                for (int nt = 0; nt < 4; ++nt)
                    #pragma unroll
                    for (int q = 0; q < 4; ++q) facc[mt][nt][q] = 0.f;

            #pragma unroll
            for (int k16 = 0; k16 < 4; ++k16) {
                unsigned Ah[2][4];
                #pragma unroll
                for (int mt = 0; mt < 2; ++mt)
                    ldsm_x4(Ah[mt], s2u(&s.u1.s2.ath[(wm2 + mt * 16 + a_r) * ATS + k16 * 16 + a_c]));
                unsigned Bh[2][4];
                #pragma unroll
                for (int g = 0; g < 2; ++g) {
                    ldsm_x4_t(Bh[g], s2u(&s.vh[(k16 * 16 + (lane & 15)) * FST +
                                               wn2 + g * 16 + (lane >> 4) * 8]));
                }
                #pragma unroll
                for (int mt = 0; mt < 2; ++mt)
                    #pragma unroll
                    for (int nt = 0; nt < 4; ++nt) {
                        const unsigned* bh = &Bh[nt >> 1][(nt & 1) * 2];
                        mma16816h(facc[mt][nt], Ah[mt], bh);
                    }
            }
            // epilogue: relu -> g_hA (fragment-paired uint4); facc + staged-x -> ah/al
            #pragma unroll
            for (int mt = 0; mt < 2; ++mt)
                #pragma unroll
                for (int nt = 0; nt < 4; ++nt) {
                    int c0 = wn2 + nt * 8 + (lane & 3) * 2;
                    int C  = head * 128 + c0;
                    int kstep = C >> 4, jj = C & 15;
                    int quad = (jj < 8) ? (jj >> 1) : ((jj - 8) >> 1);
                    int word2 = (jj < 8) ? 0 : 1;
                    #pragma unroll
                    for (int h2 = 0; h2 < 2; ++h2) {
                        int r = wm2 + mt * 16 + (lane >> 2) + h2 * 8;
                        if (r < NTOK) {
                            float v0 = facc[mt][nt][h2 * 2 + 0];
                            float v1 = facc[mt][nt][h2 * 2 + 1];
                            float r0v = fmaxf(v0, 0.f), r1v = fmaxf(v1, 0.f);
                            size_t row = (size_t)b * NTOK + r;
                            size_t tile = row >> 4;
                            int r16 = (int)(row & 15);
                            size_t idx = tile * 1024 + (size_t)kstep * 32 +
                                         (r16 & 7) * 4 + quad;
                            reinterpret_cast<unsigned*>(&g_hA[idx])[word2 * 2 + (r16 >> 3)] =
                                packh2(__float2half_rn(r0v), __float2half_rn(r1v));
                            if (head < NHEADS - 1) {
                                unsigned xh = *reinterpret_cast<unsigned*>(&s.ah[r * FST + c0]);
                                unsigned xl = *reinterpret_cast<unsigned*>(&s.al[r * FST + c0]);
                                float x0, x1;
                                recon2h(xh, xl, x0, x1);
                                v0 += x0;
                                v1 += x1;
                                unsigned hp, lp;
                                split2h(v0, v1, hp, lp);
                                *reinterpret_cast<unsigned*>(&s.ah[r * FST + c0]) = hp;
                                *reinterpret_cast<unsigned*>(&s.al[r * FST + c0]) = lp;
                            }
                        }
                    }
                }
        }
        __syncthreads();
    }
}

// ==================== Phase B: projection — fp16 1-term, LDG.128 streams ====================

__global__ void __launch_bounds__(256, 2) proj_mma_kernel(
    const float* __restrict__ proj_g, const float* __restrict__ proj_b,
    const float* __restrict__ proj_m, const float* __restrict__ proj_v,
    float* __restrict__ out)
{
    __shared__ float sPs[64], sPb[64];

    const int t = threadIdx.x, lane = t & 31, warp = t >> 5;
    const int row0 = blockIdx.y * 128, col0 = blockIdx.x * 64;

    if (t < 64) {
        int o = col0 + t;
        float sc = proj_g[o] * rsqrtf(proj_v[o] + EPS);
        sPs[t] = sc;
        sPb[t] = proj_b[o] - proj_m[o] * sc;
    }
    __syncthreads();

    const int wm = (warp >> 1) * 32, wn = (warp & 1) * 32;
    const int nb32 = blockIdx.x * 2 + (warp & 1);

    float acc[2][4][4];
    #pragma unroll
    for (int mt = 0; mt < 2; ++mt)
        #pragma unroll
        for (int nt = 0; nt < 4; ++nt)
            #pragma unroll
            for (int q = 0; q < 4; ++q) acc[mt][nt][q] = 0.f;

    const int tile0 = (row0 + wm) >> 4;

    const uint4* pA = g_hA + (size_t)tile0 * 1024 + lane;
    const uint4* pW = reinterpret_cast<const uint4*>(g_wBh) +
                      ((size_t)nb32 * 32 * 32 + lane) * 2;

    for (int ks = 0; ks < 32; ++ks) {
        uint4 A0 = pA[0];
        uint4 A1 = pA[1024];
        uint4 W01 = pW[0];
        uint4 W23 = pW[1];
        pA += 32; pW += 64;

        const unsigned* a0 = reinterpret_cast<const unsigned*>(&A0);
        const unsigned* a1 = reinterpret_cast<const unsigned*>(&A1);
        unsigned bw0[2] = {W01.x, W01.y};
        unsigned bw1[2] = {W01.z, W01.w};
        unsigned bw2[2] = {W23.x, W23.y};
        unsigned bw3[2] = {W23.z, W23.w};

        mma16816h(acc[0][0], a0, bw0);
        mma16816h(acc[0][1], a0, bw1);
        mma16816h(acc[0][2], a0, bw2);
        mma16816h(acc[0][3], a0, bw3);
        mma16816h(acc[1][0], a1, bw0);
        mma16816h(acc[1][1], a1, bw1);
        mma16816h(acc[1][2], a1, bw2);
        mma16816h(acc[1][3], a1, bw3);
    }

    const int er = lane >> 2, ec = (lane & 3) * 2;
    #pragma unroll
    for (int mt = 0; mt < 2; ++mt)
        #pragma unroll
        for (int nt = 0; nt < 4; ++nt) {
            int cl = wn + nt * 8 + ec;
            float s0 = sPs[cl], s1 = sPs[cl + 1];
            float b0 = sPb[cl], b1 = sPb[cl + 1];
            size_t gr = (size_t)(row0 + wm + mt * 16 + er) * 512 + col0 + cl;
            *reinterpret_cast<float2*>(&out[gr]) =
                make_float2(acc[mt][nt][0] * s0 + b0, acc[mt][nt][1] * s1 + b1);
            *reinterpret_cast<float2*>(&out[gr + (size_t)8 * 512]) =
                make_float2(acc[mt][nt][2] * s0 + b0, acc[mt][nt][3] * s1 + b1);
        }
}

// ==================== launch ====================

extern "C" void kernel_launch(void* const* d_in, const int* in_sizes, int n_in,
                              void* d_out, int out_size) {
    const float* x         = (const float*)d_in[0];
    const float* qkv_w     = (const float*)d_in[1];
    const float* qkv_g     = (const float*)d_in[2];
    const float* qkv_b     = (const float*)d_in[3];
    const float* qkv_m     = (const float*)d_in[4];
    const float* qkv_v     = (const float*)d_in[5];
    const float* dw_w      = (const float*)d_in[6];
    const float* dw_g      = (const float*)d_in[7];
    const float* dw_b      = (const float*)d_in[8];
    const float* dw_m      = (const float*)d_in[9];
    const float* dw_v      = (const float*)d_in[10];
    const float* proj_w    = (const float*)d_in[11];
    const float* proj_g    = (const float*)d_in[12];
    const float* proj_b    = (const float*)d_in[13];
    const float* proj_m    = (const float*)d_in[14];
    const float* proj_v    = (const float*)d_in[15];
    const float* attn_bias = (const float*)d_in[16];
    const int*   bias_idxs = (const int*)d_in[17];
    float* out = (float*)d_out;

    cudaFuncSetAttribute(cascade_kernel,
                         cudaFuncAttributeMaxDynamicSharedMemorySize,
                         (int)sizeof(SmemA));

    wsplit_kernel<<<256, 256>>>(proj_w);
    qkvsplit_kernel<<<192, 256>>>(qkv_w);

    cascade_kernel<<<BATCH, 256, sizeof(SmemA)>>>(
        x, qkv_g, qkv_b, qkv_m, qkv_v,
        dw_w, dw_g, dw_b, dw_m, dw_v, attn_bias, bias_idxs);

    proj_mma_kernel<<<dim3(8, 784), 256>>>(proj_g, proj_b, proj_m, proj_v, out);
}

// round 17
// speedup vs baseline: 1.0951x; 1.0951x over previous
#include <cuda_runtime.h>
#include <cuda_bf16.h>
#include <cuda_fp16.h>

#define BATCH   2048
#define NTOK    49
#define CH      512
#define NHEADS  4
#define KDIM    32
#define DV      128
#define QO      192
#define EPS     1e-5f
#define FST     136
#define KQS     40
#define ATS     72
#define YQS     36
#define NROWS   ((size_t)BATCH * NTOK)

// -------- global scratch (R15 layouts) --------
// h fp16 (single), proj-A-fragment tiled: [m16tile][kstep(32)][r16(16)][quad(4)] uint2
__device__ __align__(16) uint2 g_hA[NROWS * 128];
__device__ __align__(16) uint2 g_wBh[64 * 32 * 32];
__device__ __align__(16) uint2 g_qwBh[NHEADS * 24 * 8 * 32];

// ==================== helpers ====================
__device__ __forceinline__ unsigned s2u(const void* p) {
    return (unsigned)__cvta_generic_to_shared(p);
}
__device__ __forceinline__ void ldsm_x4(unsigned* r, unsigned addr) {
    asm volatile("ldmatrix.sync.aligned.m8n8.x4.shared.b16 {%0,%1,%2,%3}, [%4];"
        : "=r"(r[0]), "=r"(r[1]), "=r"(r[2]), "=r"(r[3]) : "r"(addr));
}
__device__ __forceinline__ void ldsm_x4_t(unsigned* r, unsigned addr) {
    asm volatile("ldmatrix.sync.aligned.m8n8.x4.trans.shared.b16 {%0,%1,%2,%3}, [%4];"
        : "=r"(r[0]), "=r"(r[1]), "=r"(r[2]), "=r"(r[3]) : "r"(addr));
}
__device__ __forceinline__ void mma16816h(float* c, const unsigned* a, const unsigned* b) {
    asm volatile("mma.sync.aligned.m16n8k16.row.col.f32.f16.f16.f32 "
        "{%0,%1,%2,%3}, {%4,%5,%6,%7}, {%8,%9}, {%0,%1,%2,%3};"
        : "+f"(c[0]), "+f"(c[1]), "+f"(c[2]), "+f"(c[3])
        : "r"(a[0]), "r"(a[1]), "r"(a[2]), "r"(a[3]), "r"(b[0]), "r"(b[1]));
}
__device__ __forceinline__ unsigned packh2(__half a, __half b) {
    __half2 p = __halves2half2(a, b);
    return *reinterpret_cast<unsigned*>(&p);
}
__device__ __forceinline__ void split2h(float v0, float v1, unsigned& hp, unsigned& lp) {
    __half h0 = __float2half_rn(v0), h1 = __float2half_rn(v1);
    __half l0 = __float2half_rn(v0 - __half2float(h0));
    __half l1 = __float2half_rn(v1 - __half2float(h1));
    hp = packh2(h0, h1);
    lp = packh2(l0, l1);
}
__device__ __forceinline__ void recon2h(unsigned hp, unsigned lp, float& v0, float& v1) {
    __half2 h = *reinterpret_cast<__half2*>(&hp);
    __half2 l = *reinterpret_cast<__half2*>(&lp);
    v0 = __low2float(h) + __low2float(l);
    v1 = __high2float(h) + __high2float(l);
}

// ==================== prep kernels ====================
__global__ void wsplit_kernel(const float* __restrict__ w) {
    int i = blockIdx.x * 256 + threadIdx.x;
    int j0 = i >> 10;
    int s_ = (i >> 5) & 31;
    int l  = i & 31;
    int n  = j0 * 8 + (l >> 2);
    int k0 = s_ * 16 + (l & 3) * 2;
    float a0 = w[n * 512 + k0],     a1 = w[n * 512 + k0 + 1];
    float a2 = w[n * 512 + k0 + 8], a3 = w[n * 512 + k0 + 9];
    uint2 p;
    p.x = packh2(__float2half_rn(a0), __float2half_rn(a1));
    p.y = packh2(__float2half_rn(a2), __float2half_rn(a3));
    g_wBh[i] = p;
}

__global__ void qkvsplit_kernel(const float* __restrict__ w) {
    int i = blockIdx.x * 256 + threadIdx.x;
    int h = i / (192 * 64);
    int rem = i % (192 * 64);
    int n = rem / 64;
    int p = rem % 64;
    float v0 = w[((size_t)h * 192 + n) * 128 + p * 2];
    float v1 = w[((size_t)h * 192 + n) * 128 + p * 2 + 1];
    unsigned hi = packh2(__float2half_rn(v0), __float2half_rn(v1));
    int j = n >> 3, kstep = p >> 3, q = p & 7;
    int r = q >> 2, lm4 = q & 3;
    int lane = (n & 7) * 4 + lm4;
    int base = ((h * 24 + j) * 8 + kstep) * 32 + lane;
    reinterpret_cast<unsigned*>(g_qwBh)[base * 2 + r] = hi;
}

// ==================== Phase A: cascaded heads (fp16 pipeline) ====================

struct __align__(16) SmemA {
    __half ah[64 * FST], al[64 * FST];
    __half vh[64 * FST];
    union U1 {
        struct { __half kh[64 * KQS],
                        qh[64 * KQS], ql[64 * KQS]; } s1;
        struct { __half ath[64 * ATS]; } s2;
    } u1;
    float yq[49 * YQS];
    float dww[25 * 32];
    float qscale[NHEADS * QO], qbias[NHEADS * QO];
    float dws[NHEADS * KDIM], dwb[NHEADS * KDIM];
    float ab[NHEADS * NTOK];
    unsigned char bidx[3200];
};

__global__ void __launch_bounds__(256, 2) cascade_kernel(
    const float* __restrict__ x,
    const float* __restrict__ qkv_g,  const float* __restrict__ qkv_b,
    const float* __restrict__ qkv_m,  const float* __restrict__ qkv_v,
    const float* __restrict__ dw_w,   const float* __restrict__ dw_g,
    const float* __restrict__ dw_b,   const float* __restrict__ dw_m,
    const float* __restrict__ dw_v,   const float* __restrict__ attn_bias,
    const int* __restrict__ bias_idxs)
{
    extern __shared__ unsigned char smem_raw[];
    SmemA& s = *reinterpret_cast<SmemA*>(smem_raw);
    const int t    = threadIdx.x;
    const int b    = blockIdx.x;
    const int lane = t & 31;
    const int warp = t >> 5;
    const float scale = rsqrtf((float)KDIM);
    const size_t xoff = (size_t)b * NTOK * CH;

    for (int j = t; j < NHEADS * NTOK; j += 256) s.ab[j] = attn_bias[j];
    for (int j = t; j < NTOK * NTOK; j += 256) s.bidx[j] = (unsigned char)bias_idxs[j];
    for (int j = t; j < NHEADS * QO; j += 256) {
        float sc = qkv_g[j] * rsqrtf(qkv_v[j] + EPS);
        s.qscale[j] = sc;
        s.qbias[j]  = qkv_b[j] - qkv_m[j] * sc;
    }
    if (t < NHEADS * KDIM) {
        float sc = dw_g[t] * rsqrtf(dw_v[t] + EPS);
        s.dws[t] = sc;
        s.dwb[t] = dw_b[t] - dw_m[t] * sc;
    }
    for (int j = t; j < 15 * FST; j += 256) {
        __half z = __float2half_rn(0.f);
        s.ah[49 * FST + j] = z; s.al[49 * FST + j] = z;
        s.vh[49 * FST + j] = z;
    }
    for (int c = t; c < 1568; c += 256) {
        int n = c >> 5, d4 = (c & 31) * 4;
        float4 xv = *reinterpret_cast<const float4*>(&x[xoff + n * CH + d4]);
        unsigned hp0, lp0, hp1, lp1;
        split2h(xv.x, xv.y, hp0, lp0);
        split2h(xv.z, xv.w, hp1, lp1);
        *reinterpret_cast<uint2*>(&s.ah[n * FST + d4]) = make_uint2(hp0, hp1);
        *reinterpret_cast<uint2*>(&s.al[n * FST + d4]) = make_uint2(lp0, lp1);
    }

    const int a_r = lane & 15, a_c = (lane >> 4) * 8;
    const int b_r = (lane & 7) + ((lane & 16) ? 8 : 0);
    const int b_c = (lane & 8) ? 8 : 0;
    __syncthreads();

    for (int head = 0; head < NHEADS; ++head) {
        for (int j = t; j < KDIM * 25; j += 256) {
            int c = j / 25, tap = j % 25;
            s.dww[tap * 32 + c] = dw_w[(head * KDIM + c) * 25 + tap];
        }

        // ================= qkv GEMM (fp16 2-term) =================
        {
            float qacc[4][3][4];
            #pragma unroll
            for (int m = 0; m < 4; ++m)
                #pragma unroll
                for (int j = 0; j < 3; ++j)
                    #pragma unroll
                    for (int q = 0; q < 4; ++q) qacc[m][j][q] = 0.f;

            const int wbase = (head * 24 + warp * 3) * 8;
            uint2 b0[3], b1[3];
            #pragma unroll
            for (int j = 0; j < 3; ++j) {
                b0[j] = g_qwBh[(wbase + j * 8 + 0) * 32 + lane];
                b1[j] = g_qwBh[(wbase + j * 8 + 1) * 32 + lane];
            }
            #pragma unroll
            for (int k = 0; k < 8; ++k) {
                uint2 tb[3];
                if (k < 6) {
                    #pragma unroll
                    for (int j = 0; j < 3; ++j)
                        tb[j] = g_qwBh[(wbase + j * 8 + k + 2) * 32 + lane];
                }
                uint2* bc = (k & 1) ? b1 : b0;
                #pragma unroll
                for (int m = 0; m < 4; ++m) {
                    unsigned Ah[4], Al[4];
                    ldsm_x4(Ah, s2u(&s.ah[(m * 16 + a_r) * FST + k * 16 + a_c]));
                    ldsm_x4(Al, s2u(&s.al[(m * 16 + a_r) * FST + k * 16 + a_c]));
                    #pragma unroll
                    for (int j = 0; j < 3; ++j) {
                        mma16816h(qacc[m][j], Ah, reinterpret_cast<const unsigned*>(&bc[j]));
                        mma16816h(qacc[m][j], Al, reinterpret_cast<const unsigned*>(&bc[j]));
                    }
                }
                if (k < 6) {
                    #pragma unroll
                    for (int j = 0; j < 3; ++j) {
                        if (k & 1) b1[j] = tb[j]; else b0[j] = tb[j];
                    }
                }
            }
            const float* qsc = s.qscale + head * QO;
            const float* qbs = s.qbias  + head * QO;
            #pragma unroll
            for (int m = 0; m < 4; ++m) {
                int rb = m * 16 + (lane >> 2);
                #pragma unroll
                for (int j = 0; j < 3; ++j) {
                    int c0 = warp * 24 + j * 8 + (lane & 3) * 2;
                    float sc0 = qsc[c0], sc1 = qsc[c0 + 1];
                    float bb0 = qbs[c0], bb1 = qbs[c0 + 1];
                    #pragma unroll
                    for (int h2 = 0; h2 < 2; ++h2) {
                        int r = rb + h2 * 8;
                        if (r < NTOK) {
                            float y0 = qacc[m][j][h2 * 2 + 0] * sc0 + bb0;
                            float y1 = qacc[m][j][h2 * 2 + 1] * sc1 + bb1;
                            if (c0 < 32) {
                                s.yq[r * YQS + c0]     = y0;
                                s.yq[r * YQS + c0 + 1] = y1;
                            } else if (c0 < 64) {
                                *reinterpret_cast<unsigned*>(&s.u1.s1.kh[r * KQS + c0 - 32]) =
                                    packh2(__float2half_rn(y0), __float2half_rn(y1));
                            } else {
                                *reinterpret_cast<unsigned*>(&s.vh[r * FST + c0 - 64]) =
                                    packh2(__float2half_rn(y0), __float2half_rn(y1));
                            }
                        }
                    }
                }
            }
        }
        __syncthreads();

        // ================= depthwise conv (+BN) only =================
        for (int idx = t; idx < 392; idx += 256) {
            int n = idx >> 3, g = (idx & 7) * 4;
            int r = n / 7, sc_ = n % 7;
            float s0 = 0.f, s1 = 0.f, s2v = 0.f, s3 = 0.f;
            #pragma unroll
            for (int a = 0; a < 5; ++a) {
                int rr = r + a - 2;
                if ((unsigned)rr < 7u) {
                    #pragma unroll
                    for (int bb = 0; bb < 5; ++bb) {
                        int ss = sc_ + bb - 2;
                        if ((unsigned)ss < 7u) {
                            float4 yv = *reinterpret_cast<const float4*>(
                                &s.yq[(rr * 7 + ss) * YQS + g]);
                            float4 wv = *reinterpret_cast<const float4*>(
                                &s.dww[(a * 5 + bb) * 32 + g]);
                            s0 += yv.x * wv.x; s1 += yv.y * wv.y;
                            s2v += yv.z * wv.z; s3 += yv.w * wv.w;
                        }
                    }
                }
            }
            float4 dsv = *reinterpret_cast<const float4*>(&s.dws[head * KDIM + g]);
            float4 dbv = *reinterpret_cast<const float4*>(&s.dwb[head * KDIM + g]);
            float q0 = s0 * dsv.x + dbv.x, q1 = s1 * dsv.y + dbv.y;
            float q2 = s2v * dsv.z + dbv.z, q3 = s3 * dsv.w + dbv.w;
            unsigned hp0, lp0, hp1, lp1;
            split2h(q0, q1, hp0, lp0);
            split2h(q2, q3, hp1, lp1);
            *reinterpret_cast<uint2*>(&s.u1.s1.qh[n * KQS + g]) = make_uint2(hp0, hp1);
            *reinterpret_cast<uint2*>(&s.u1.s1.ql[n * KQS + g]) = make_uint2(lp0, lp1);
        }
        __syncthreads();

        // ================= qk+softmax (warps 0-3) ‖ x_next staging (warps 4-7) ==========
        if (warp < 4) {
            const int wm = warp * 16;
            float sacc[8][4];
            #pragma unroll
            for (int nt = 0; nt < 8; ++nt)
                #pragma unroll
                for (int q = 0; q < 4; ++q) sacc[nt][q] = 0.f;

            #pragma unroll
            for (int k16 = 0; k16 < 2; ++k16) {
                unsigned Ah[4], Al[4];
                ldsm_x4(Ah, s2u(&s.u1.s1.qh[(wm + a_r) * KQS + k16 * 16 + a_c]));
                ldsm_x4(Al, s2u(&s.u1.s1.ql[(wm + a_r) * KQS + k16 * 16 + a_c]));
                unsigned Bh[4][4];
                #pragma unroll
                for (int g = 0; g < 4; ++g)
                    ldsm_x4(Bh[g], s2u(&s.u1.s1.kh[(g * 16 + b_r) * KQS + k16 * 16 + b_c]));
                #pragma unroll
                for (int nt = 0; nt < 8; ++nt) {
                    const unsigned* bh = &Bh[nt >> 1][(nt & 1) * 2];
                    mma16816h(sacc[nt], Ah, bh);
                    mma16816h(sacc[nt], Al, bh);
                }
            }
            asm volatile("bar.sync 1, 128;" ::: "memory");

            const float* abr = s.ab + head * NTOK;
            const int r0 = wm + (lane >> 2);
            const int cq = (lane & 3) * 2;
            #pragma unroll
            for (int h2 = 0; h2 < 2; ++h2) {
                int r = r0 + h2 * 8;
                int rbase = r * 49;
                float v[16];
                #pragma unroll
                for (int nt = 0; nt < 8; ++nt) {
                    #pragma unroll
                    for (int q = 0; q < 2; ++q) {
                        int c = nt * 8 + cq + q;
                        v[nt * 2 + q] = (c < NTOK)
                            ? fmaf(sacc[nt][h2 * 2 + q], scale, abr[s.bidx[rbase + c]])
                            : -1e30f;
                    }
                }
                float mx = v[0];
                #pragma unroll
                for (int i = 1; i < 16; ++i) mx = fmaxf(mx, v[i]);
                mx = fmaxf(mx, __shfl_xor_sync(0xffffffffu, mx, 1));
                mx = fmaxf(mx, __shfl_xor_sync(0xffffffffu, mx, 2));
                float sm = 0.f;
                #pragma unroll
                for (int i = 0; i < 16; ++i) { v[i] = __expf(v[i] - mx); sm += v[i]; }
                sm += __shfl_xor_sync(0xffffffffu, sm, 1);
                sm += __shfl_xor_sync(0xffffffffu, sm, 2);
                float inv = __frcp_rn(sm);
                #pragma unroll
                for (int nt = 0; nt < 8; ++nt) {
                    *reinterpret_cast<unsigned*>(&s.u1.s2.ath[r * ATS + nt * 8 + cq]) =
                        packh2(__float2half_rn(v[nt * 2] * inv),
                               __float2half_rn(v[nt * 2 + 1] * inv));
                }
            }
        } else if (head < NHEADS - 1) {
            // warps 4-7: stage next head's x into ah/al (feat already consumed)
            for (int c = t - 128; c < 1568; c += 128) {
                int n = c >> 5, d4 = (c & 31) * 4;
                float4 xv = *reinterpret_cast<const float4*>(
                    &x[xoff + n * CH + (head + 1) * 128 + d4]);
                unsigned hp0, lp0, hp1, lp1;
                split2h(xv.x, xv.y, hp0, lp0);
                split2h(xv.z, xv.w, hp1, lp1);
                *reinterpret_cast<uint2*>(&s.ah[n * FST + d4]) = make_uint2(hp0, hp1);
                *reinterpret_cast<uint2*>(&s.al[n * FST + d4]) = make_uint2(lp0, lp1);
            }
        }
        __syncthreads();

        // ================= attn @ v (fp16 1-term probs) + staged-x add =================
        {
            const int wm2 = (warp & 1) * 32, wn2 = (warp >> 1) * 32;
            float facc[2][4][4];
            #pragma unroll
            for (int mt = 0; mt < 2; ++mt)
                #pragma unroll
                for (int nt = 0; nt < 4; ++nt)
                    #pragma unroll
                    for (int q = 0; q < 4; ++q) facc[mt][nt][q] = 0.f;

            #pragma unroll
            for (int k16 = 0; k16 < 4; ++k16) {
                unsigned Ah[2][4];
                #pragma unroll
                for (int mt = 0; mt < 2; ++mt)
                    ldsm_x4(Ah[mt], s2u(&s.u1.s2.ath[(wm2 + mt * 16 + a_r) * ATS + k16 * 16 + a_c]));
                unsigned Bh[2][4];
                #pragma unroll
                for (int g = 0; g < 2; ++g) {
                    ldsm_x4_t(Bh[g], s2u(&s.vh[(k16 * 16 + (lane & 15)) * FST +
                                               wn2 + g * 16 + (lane >> 4) * 8]));
                }
                #pragma unroll
                for (int mt = 0; mt < 2; ++mt)
                    #pragma unroll
                    for (int nt = 0; nt < 4; ++nt) {
                        const unsigned* bh = &Bh[nt >> 1][(nt & 1) * 2];
                        mma16816h(facc[mt][nt], Ah[mt], bh);
                    }
            }
            // epilogue: relu -> g_hA (fp16 single, R15 layout); facc + staged-x -> ah/al
            #pragma unroll
            for (int mt = 0; mt < 2; ++mt)
                #pragma unroll
                for (int nt = 0; nt < 4; ++nt) {
                    int c0 = wn2 + nt * 8 + (lane & 3) * 2;
                    int C  = head * 128 + c0;
                    int kstep = C >> 4, jj = C & 15;
                    int quad = (jj < 8) ? (jj >> 1) : ((jj - 8) >> 1);
                    int word = (jj < 8) ? 0 : 1;
                    #pragma unroll
                    for (int h2 = 0; h2 < 2; ++h2) {
                        int r = wm2 + mt * 16 + (lane >> 2) + h2 * 8;
                        if (r < NTOK) {
                            float v0 = facc[mt][nt][h2 * 2 + 0];
                            float v1 = facc[mt][nt][h2 * 2 + 1];
                            float r0v = fmaxf(v0, 0.f), r1v = fmaxf(v1, 0.f);
                            size_t row = (size_t)b * NTOK + r;
                            size_t idx = (row >> 4) * 2048 + (size_t)kstep * 64 +
                                         (row & 15) * 4 + quad;
                            reinterpret_cast<unsigned*>(&g_hA[idx])[word] =
                                packh2(__float2half_rn(r0v), __float2half_rn(r1v));
                            if (head < NHEADS - 1) {
                                unsigned xh = *reinterpret_cast<unsigned*>(&s.ah[r * FST + c0]);
                                unsigned xl = *reinterpret_cast<unsigned*>(&s.al[r * FST + c0]);
                                float x0, x1;
                                recon2h(xh, xl, x0, x1);
                                v0 += x0;
                                v1 += x1;
                                unsigned hp, lp;
                                split2h(v0, v1, hp, lp);
                                *reinterpret_cast<unsigned*>(&s.ah[r * FST + c0]) = hp;
                                *reinterpret_cast<unsigned*>(&s.al[r * FST + c0]) = lp;
                            }
                        }
                    }
                }
        }
        __syncthreads();
    }
}

// ==================== Phase B: projection — fp16 single-A, 1-term (R15 form) ====================

__global__ void __launch_bounds__(256, 2) proj_mma_kernel(
    const float* __restrict__ proj_g, const float* __restrict__ proj_b,
    const float* __restrict__ proj_m, const float* __restrict__ proj_v,
    float* __restrict__ out)
{
    __shared__ float sPs[64], sPb[64];

    const int t = threadIdx.x, lane = t & 31, warp = t >> 5;
    const int row0 = blockIdx.y * 128, col0 = blockIdx.x * 64;

    if (t < 64) {
        int o = col0 + t;
        float sc = proj_g[o] * rsqrtf(proj_v[o] + EPS);
        sPs[t] = sc;
        sPb[t] = proj_b[o] - proj_m[o] * sc;
    }
    __syncthreads();

    const int wm = (warp >> 1) * 32, wn = (warp & 1) * 32;
    const int nb = (col0 >> 3) + (wn >> 3);

    float acc[2][4][4];
    #pragma unroll
    for (int mt = 0; mt < 2; ++mt)
        #pragma unroll
        for (int nt = 0; nt < 4; ++nt)
            #pragma unroll
            for (int q = 0; q < 4; ++q) acc[mt][nt][q] = 0.f;

    const int tile0 = (row0 + wm) >> 4;

    const uint2* pA = g_hA + (size_t)tile0 * 2048 + lane;
    const uint2* pW = g_wBh + (size_t)nb * 1024 + lane;

    for (int ks = 0; ks < 32; ++ks) {
        unsigned Ah[2][4];
        {
            uint2 U0 = pA[0], U1 = pA[32];
            Ah[0][0] = U0.x; Ah[0][1] = U1.x; Ah[0][2] = U0.y; Ah[0][3] = U1.y;
            uint2 V0 = pA[2048], V1 = pA[2080];
            Ah[1][0] = V0.x; Ah[1][1] = V1.x; Ah[1][2] = V0.y; Ah[1][3] = V1.y;
        }
        uint2 W[4];
        W[0] = pW[0]; W[1] = pW[1024]; W[2] = pW[2048]; W[3] = pW[3072];
        pA += 64; pW += 32;

        #pragma unroll
        for (int mt = 0; mt < 2; ++mt)
            #pragma unroll
            for (int nt = 0; nt < 4; ++nt)
                mma16816h(acc[mt][nt], Ah[mt],
                          reinterpret_cast<const unsigned*>(&W[nt]));
    }

    const int er = lane >> 2, ec = (lane & 3) * 2;
    #pragma unroll
    for (int mt = 0; mt < 2; ++mt)
        #pragma unroll
        for (int nt = 0; nt < 4; ++nt) {
            int cl = wn + nt * 8 + ec;
            float s0 = sPs[cl], s1 = sPs[cl + 1];
            float b0 = sPb[cl], b1 = sPb[cl + 1];
            size_t gr = (size_t)(row0 + wm + mt * 16 + er) * 512 + col0 + cl;
            *reinterpret_cast<float2*>(&out[gr]) =
                make_float2(acc[mt][nt][0] * s0 + b0, acc[mt][nt][1] * s1 + b1);
            *reinterpret_cast<float2*>(&out[gr + (size_t)8 * 512]) =
                make_float2(acc[mt][nt][2] * s0 + b0, acc[mt][nt][3] * s1 + b1);
        }
}

// ==================== launch ====================

extern "C" void kernel_launch(void* const* d_in, const int* in_sizes, int n_in,
                              void* d_out, int out_size) {
    const float* x         = (const float*)d_in[0];
    const float* qkv_w     = (const float*)d_in[1];
    const float* qkv_g     = (const float*)d_in[2];
    const float* qkv_b     = (const float*)d_in[3];
    const float* qkv_m     = (const float*)d_in[4];
    const float* qkv_v     = (const float*)d_in[5];
    const float* dw_w      = (const float*)d_in[6];
    const float* dw_g      = (const float*)d_in[7];
    const float* dw_b      = (const float*)d_in[8];
    const float* dw_m      = (const float*)d_in[9];
    const float* dw_v      = (const float*)d_in[10];
    const float* proj_w    = (const float*)d_in[11];
    const float* proj_g    = (const float*)d_in[12];
    const float* proj_b    = (const float*)d_in[13];
    const float* proj_m    = (const float*)d_in[14];
    const float* proj_v    = (const float*)d_in[15];
    const float* attn_bias = (const float*)d_in[16];
    const int*   bias_idxs = (const int*)d_in[17];
    float* out = (float*)d_out;

    cudaFuncSetAttribute(cascade_kernel,
                         cudaFuncAttributeMaxDynamicSharedMemorySize,
                         (int)sizeof(SmemA));

    wsplit_kernel<<<256, 256>>>(proj_w);
    qkvsplit_kernel<<<192, 256>>>(qkv_w);

    cascade_kernel<<<BATCH, 256, sizeof(SmemA)>>>(
        x, qkv_g, qkv_b, qkv_m, qkv_v,
        dw_w, dw_g, dw_b, dw_m, dw_v, attn_bias, bias_idxs);

    proj_mma_kernel<<<dim3(8, 784), 256>>>(proj_g, proj_b, proj_m, proj_v, out);
}